// round 14
// baseline (speedup 1.0000x reference)
#include <cuda_runtime.h>
#include <cstdint>
#include <cstddef>

// Problem dims
#define T_STEPS 512
#define BATCH   256
#define NF      160
#define H       128
#define GC      512   // 4*H gate columns

#define TEAMS 32
#define ROWS_PER_TEAM 8
#define UNITS_PER_CTA 32
#define HB 1024   // floats per h buffer (8 rows x 128)

// -------- global scratch (static __device__, allocation-free) --------
// Layout: [t][b][unit(128)][gate(4)] -> coalesced float4 read per (b,unit)
__device__ float g_xpre[(size_t)T_STEPS * BATCH * GC];       // 256 MB

// ---------------- f32x2 helpers ----------------
__device__ __forceinline__ void ffma2(unsigned long long& d,
                                      unsigned long long a,
                                      unsigned long long b) {
    asm("fma.rn.f32x2 %0, %1, %2, %0;" : "+l"(d) : "l"(a), "l"(b));
}
__device__ __forceinline__ float hsum2(unsigned long long v) {
    unsigned lo, hi;
    asm("mov.b64 {%0,%1}, %2;" : "=r"(lo), "=r"(hi) : "l"(v));
    return __uint_as_float(lo) + __uint_as_float(hi);
}

// ---------------- cluster helpers ----------------
__device__ __forceinline__ void cluster_sync_() {
    asm volatile("barrier.cluster.arrive.aligned;" ::: "memory");
    asm volatile("barrier.cluster.wait.aligned;" ::: "memory");
}
__device__ __forceinline__ unsigned ctarank_() {
    unsigned r;
    asm("mov.u32 %0, %%cluster_ctarank;" : "=r"(r));
    return r;
}
__device__ __forceinline__ void st_peer_f32(uint32_t local_smem_addr, int rank, float v) {
    uint32_t ra;
    asm("mapa.shared::cluster.u32 %0, %1, %2;" : "=r"(ra) : "r"(local_smem_addr), "r"(rank));
    asm volatile("st.shared::cluster.f32 [%0], %1;" :: "r"(ra), "f"(v) : "memory");
}

// Swizzled weight layout: col row = 128 floats = 32 chunks of 16B.
__device__ __forceinline__ int wswz(int col, int k) {
    return col * 128 + (((k >> 2) ^ (col & 7)) << 2);
}

// ---------------- fast activations (tanh.approx, sm_75+) ----------------
__device__ __forceinline__ float tanh_fast(float x) {
    float y;
    asm("tanh.approx.f32 %0, %1;" : "=f"(y) : "f"(x));
    return y;
}
__device__ __forceinline__ float sigm(float v)  { return 0.5f * tanh_fast(0.5f * v) + 0.5f; }
__device__ __forceinline__ float tanhx(float v) { return tanh_fast(v); }

// ---------------------------------------------------------------
// Precompute: Xpre[t][b][unit][gate] = x[b][t][:] @ Wih0[gate*128+?][:] + biases
#define PRE_SMEM (2 * 64 * 164 * 4)
__global__ __launch_bounds__(256) void precompute_kernel(
    const float* __restrict__ x,
    const float* __restrict__ Wih0,
    const float* __restrict__ bih0,
    const float* __restrict__ bhh0)
{
    extern __shared__ float sm[];
    float* xs = sm;              // [64][164]
    float* ws = sm + 64 * 164;   // [64][164]

    const int t   = blockIdx.x;
    const int b0  = blockIdx.y * 64;
    const int gc0 = blockIdx.z * 64;
    const int tid = threadIdx.x;

    for (int idx = tid; idx < 64 * 40; idx += 256) {
        int row = idx / 40;
        int q   = (idx % 40) * 4;
        *(float4*)&xs[row * 164 + q] =
            *(const float4*)&x[((size_t)(b0 + row) * T_STEPS + t) * NF + q];
        *(float4*)&ws[row * 164 + q] =
            *(const float4*)&Wih0[(size_t)(gc0 + row) * NF + q];
    }
    __syncthreads();

    const int tx = tid & 15;
    const int ty = tid >> 4;

    unsigned long long acc[4][4];
#pragma unroll
    for (int i = 0; i < 4; i++)
#pragma unroll
        for (int j = 0; j < 4; j++) acc[i][j] = 0ull;

#pragma unroll 4
    for (int k = 0; k < NF; k += 4) {
        ulonglong2 av[4], bv[4];
#pragma unroll
        for (int i = 0; i < 4; i++) av[i] = *(const ulonglong2*)&xs[(ty + 16 * i) * 164 + k];
#pragma unroll
        for (int j = 0; j < 4; j++) bv[j] = *(const ulonglong2*)&ws[(tx + 16 * j) * 164 + k];
#pragma unroll
        for (int i = 0; i < 4; i++)
#pragma unroll
            for (int j = 0; j < 4; j++) {
                ffma2(acc[i][j], av[i].x, bv[j].x);
                ffma2(acc[i][j], av[i].y, bv[j].y);
            }
    }

#pragma unroll
    for (int i = 0; i < 4; i++) {
        int b = b0 + ty + 16 * i;
#pragma unroll
        for (int j = 0; j < 4; j++) {
            int gc = gc0 + tx + 16 * j;
            float bias = __ldg(&bih0[gc]) + __ldg(&bhh0[gc]);
            int unit = gc & 127;
            int gate = gc >> 7;
            g_xpre[(((size_t)t * BATCH + b) * 128 + unit) * 4 + gate] =
                hsum2(acc[i][j]) + bias;
        }
    }
}

// ---------------------------------------------------------------
// smem: 3 swizzled weight slices + 2x2 h buffers + shared gs + bias = 229888 B
#define REC_SMEM ((3 * 128 * 128 + 2 * HB + 2 * HB + 4 * 1024 + 128) * 4)

__global__ __launch_bounds__(384, 1) __cluster_dims__(4, 1, 1)
void lstm_recurrent_kernel(
    const float* __restrict__ h0,
    const float* __restrict__ c0,
    const float* __restrict__ Whh0,
    const float* __restrict__ Wih1,
    const float* __restrict__ Whh1,
    const float* __restrict__ bih1,
    const float* __restrict__ bhh1,
    float* __restrict__ out)
{
    extern __shared__ float sm[];
    float* w0  = sm;                   // [128 cols][128] swizzled W_hh0 slice
    float* w1i = w0  + 128 * 128;
    float* w1h = w1i + 128 * 128;
    float* h1b = w1h + 128 * 128;      // [2][8][128]
    float* h2b = h1b + 2 * HB;         // [2][8][128]
    float* gs  = h2b + 2 * HB;         // [4 kp][8][128] shared staging (A then B)
    float* b1s = gs  + 4 * 1024;       // [128]

    const int tid   = threadIdx.x;
    const int team  = blockIdx.x >> 2;
    const int rank  = (int)ctarank_();
    const int brow0 = team * ROWS_PER_TEAM;
    const int ubase = rank * UNITS_PER_CTA;

    // --- load weight slices into swizzled smem (local col j = gate*32+unit) ---
    for (int idx = tid; idx < 128 * 32; idx += 384) {
        int j = idx >> 5;           // local col
        int q = idx & 31;           // 16B chunk
        int grow = (j >> 5) * H + ubase + (j & 31);
        int dst = j * 128 + ((q ^ (j & 7)) << 2);
        *(float4*)&w0 [dst] = *(const float4*)&Whh0[(size_t)grow * H + q * 4];
        *(float4*)&w1i[dst] = *(const float4*)&Wih1[(size_t)grow * H + q * 4];
        *(float4*)&w1h[dst] = *(const float4*)&Whh1[(size_t)grow * H + q * 4];
    }
    for (int j = tid; j < 128; j += 384) {
        int grow = (j >> 5) * H + ubase + (j & 31);
        b1s[j] = bih1[grow] + bhh1[grow];
    }
    // initial h: h1[-1] -> h1b buf0, h2[-1] -> h2b buf0
    for (int idx = tid; idx < 8 * 32; idx += 384) {
        int r = idx >> 5;
        int q = (idx & 31) * 4;
        *(float4*)&h1b[r * 128 + q] = *(const float4*)&h0[((size_t)(brow0 + r)) * H + q];
        *(float4*)&h2b[r * 128 + q] = *(const float4*)&h0[((size_t)(BATCH + brow0 + r)) * H + q];
    }
    __syncthreads();

    // pointwise mapping (threads 0-255 do BOTH layers' pointwise)
    const int pr = (tid >> 5) & 7;
    const int pu = tid & 31;
    float c1 = 0.f, c2 = 0.f, bb0 = 0.f, bb1 = 0.f, bb2 = 0.f, bb3 = 0.f;
    if (tid < 256) {
        c1 = c0[((size_t)(brow0 + pr)) * H + ubase + pu];
        c2 = c0[((size_t)(BATCH + brow0 + pr)) * H + ubase + pu];
        bb0 = b1s[      pu];
        bb1 = b1s[ 32 + pu];
        bb2 = b1s[ 64 + pu];
        bb3 = b1s[ 96 + pu];
    }
    cluster_sync_();

    // GEMM warp roles
    const int warp = tid >> 5;
    const int lane = tid & 31;
    const bool isA = (warp < 4);
    const int kbA = warp * 32;
    const int w4  = warp - 4;
    const int kbB = (w4 >> 1) * 32;
    const int cgB = ((w4 & 1) << 5) + lane;

    const uint32_t h1a0 = (uint32_t)__cvta_generic_to_shared(&h1b[pr * 128 + ubase + pu]);
    const uint32_t h1a1 = h1a0 + HB * 4;
    const uint32_t h2a0 = (uint32_t)__cvta_generic_to_shared(&h2b[pr * 128 + ubase + pu]);
    const uint32_t h2a1 = h2a0 + HB * 4;

    // ---------------- Prologue: gemmA(0) + h1(0) -> h1b buf1 ----------------
    {
        if (isA) {
            unsigned long long acc[4][8];
#pragma unroll
            for (int j = 0; j < 4; j++)
#pragma unroll
                for (int r = 0; r < 8; r++) acc[j][r] = 0ull;
#pragma unroll
            for (int ch = 0; ch < 8; ch++) {
                int k = kbA + ch * 4;
                ulonglong2 hv[8];
#pragma unroll
                for (int r = 0; r < 8; r++) hv[r] = *(const ulonglong2*)&h1b[r * 128 + k];
#pragma unroll
                for (int j = 0; j < 4; j++) {
                    ulonglong2 wv = *(const ulonglong2*)&w0[wswz(lane + 32 * j, k)];
#pragma unroll
                    for (int r = 0; r < 8; r++) {
                        ffma2(acc[j][r], wv.x, hv[r].x);
                        ffma2(acc[j][r], wv.y, hv[r].y);
                    }
                }
            }
#pragma unroll
            for (int j = 0; j < 4; j++)
#pragma unroll
                for (int r = 0; r < 8; r++)
                    gs[warp * 1024 + r * 128 + 32 * j + lane] = hsum2(acc[j][r]);
        }
        __syncthreads();
        if (tid < 256) {
            float4 xg = __ldg((const float4*)
                &g_xpre[(((size_t)(brow0 + pr)) * 128 + ubase + pu) * 4]);
            float gi = xg.x, gf = xg.y, gg = xg.z, go = xg.w;
#pragma unroll
            for (int q = 0; q < 4; q++) {
                const float* gq = &gs[q * 1024 + pr * 128];
                gi += gq[      pu];
                gf += gq[ 32 + pu];
                gg += gq[ 64 + pu];
                go += gq[ 96 + pu];
            }
            float iv = sigm(gi), fv = sigm(gf), gv = tanhx(gg), ov = sigm(go);
            c1 = fv * c1 + iv * gv;
            float h1v = ov * tanhx(c1);
#pragma unroll
            for (int rk = 0; rk < 4; rk++) st_peer_f32(h1a1, rk, h1v);  // buf1
        }
        cluster_sync_();
    }

    // ---------- Main loop: iteration i computes h2(i) and h1(i+1) ----------
    for (int i = 0; i < T_STEPS; i++) {
        const int p = i & 1;
        const float* h1cur = h1b + (p ^ 1) * HB;   // h1[i]
        const float* h2cur = h2b + p * HB;         // h2[i-1]

        // prefetch xpre[i+1] gates as one float4 (hidden behind GEMM burst)
        float xg0 = 0.f, xg1 = 0.f, xg2 = 0.f, xg3 = 0.f;
        if (tid < 256 && i < T_STEPS - 1) {
            float4 xg = __ldg((const float4*)
                &g_xpre[(((size_t)(i + 1) * BATCH + brow0 + pr) * 128 + ubase + pu) * 4]);
            xg0 = xg.x; xg1 = xg.y; xg2 = xg.z; xg3 = xg.w;
        }

        unsigned long long accB[2][8];
        if (isA) {
            // ---- gemmA: W_hh0 . h1[i], 4 cols x 8 rows x 32k ----
            unsigned long long acc[4][8];
#pragma unroll
            for (int j = 0; j < 4; j++)
#pragma unroll
                for (int r = 0; r < 8; r++) acc[j][r] = 0ull;
#pragma unroll
            for (int ch = 0; ch < 8; ch++) {
                int k = kbA + ch * 4;
                ulonglong2 hv[8];
#pragma unroll
                for (int r = 0; r < 8; r++) hv[r] = *(const ulonglong2*)&h1cur[r * 128 + k];
#pragma unroll
                for (int j = 0; j < 4; j++) {
                    ulonglong2 wv = *(const ulonglong2*)&w0[wswz(lane + 32 * j, k)];
#pragma unroll
                    for (int r = 0; r < 8; r++) {
                        ffma2(acc[j][r], wv.x, hv[r].x);
                        ffma2(acc[j][r], wv.y, hv[r].y);
                    }
                }
            }
#pragma unroll
            for (int j = 0; j < 4; j++)
#pragma unroll
                for (int r = 0; r < 8; r++)
                    gs[warp * 1024 + r * 128 + 32 * j + lane] = hsum2(acc[j][r]);
        } else {
            // ---- gemmB merged: per-ch interleave of W_ih1.h1[i] and W_hh1.h2[i-1] ----
#pragma unroll
            for (int j = 0; j < 2; j++)
#pragma unroll
                for (int r = 0; r < 8; r++) accB[j][r] = 0ull;
#pragma unroll
            for (int ch = 0; ch < 8; ch++) {
                int k = kbB + ch * 4;
                {
                    ulonglong2 hv[8];
#pragma unroll
                    for (int r = 0; r < 8; r++) hv[r] = *(const ulonglong2*)&h1cur[r * 128 + k];
#pragma unroll
                    for (int j = 0; j < 2; j++) {
                        ulonglong2 wv = *(const ulonglong2*)&w1i[wswz(cgB + 64 * j, k)];
#pragma unroll
                        for (int r = 0; r < 8; r++) {
                            ffma2(accB[j][r], wv.x, hv[r].x);
                            ffma2(accB[j][r], wv.y, hv[r].y);
                        }
                    }
                }
                {
                    ulonglong2 hv[8];
#pragma unroll
                    for (int r = 0; r < 8; r++) hv[r] = *(const ulonglong2*)&h2cur[r * 128 + k];
#pragma unroll
                    for (int j = 0; j < 2; j++) {
                        ulonglong2 wv = *(const ulonglong2*)&w1h[wswz(cgB + 64 * j, k)];
#pragma unroll
                        for (int r = 0; r < 8; r++) {
                            ffma2(accB[j][r], wv.x, hv[r].x);
                            ffma2(accB[j][r], wv.y, hv[r].y);
                        }
                    }
                }
            }
        }
        __syncthreads();   // A partials visible; B still holds accB in regs

        // ---- pointwise layer-0 -> h1[i+1] ----
        if (tid < 256 && i < T_STEPS - 1) {
            float gi = xg0, gf = xg1, gg = xg2, go = xg3;
#pragma unroll
            for (int q = 0; q < 4; q++) {
                const float* gq = &gs[q * 1024 + pr * 128];
                gi += gq[      pu];
                gf += gq[ 32 + pu];
                gg += gq[ 64 + pu];
                go += gq[ 96 + pu];
            }
            float iv = sigm(gi), fv = sigm(gf), gv = tanhx(gg), ov = sigm(go);
            c1 = fv * c1 + iv * gv;
            float h1v = ov * tanhx(c1);
            uint32_t a = p ? h1a1 : h1a0;
#pragma unroll
            for (int rk = 0; rk < 4; rk++) st_peer_f32(a, rk, h1v);
        }
        __syncthreads();   // gs reads done; B may overwrite

        if (!isA) {
#pragma unroll
            for (int j = 0; j < 2; j++)
#pragma unroll
                for (int r = 0; r < 8; r++)
                    gs[kbB * 32 + r * 128 + cgB + 64 * j] = hsum2(accB[j][r]);
        }
        __syncthreads();   // B partials visible

        // ---- pointwise layer-1 -> h2[i] ----
        if (tid < 256) {
            float gi = bb0, gf = bb1, gg = bb2, go = bb3;
#pragma unroll
            for (int q = 0; q < 4; q++) {
                const float* gq = &gs[q * 1024 + pr * 128];
                gi += gq[      pu];
                gf += gq[ 32 + pu];
                gg += gq[ 64 + pu];
                go += gq[ 96 + pu];
            }
            float iv = sigm(gi), fv = sigm(gf), gv = tanhx(gg), ov = sigm(go);
            c2 = fv * c2 + iv * gv;
            float h2v = ov * tanhx(c2);
            uint32_t a = p ? h2a0 : h2a1;
#pragma unroll
            for (int rk = 0; rk < 4; rk++) st_peer_f32(a, rk, h2v);
            if (i == T_STEPS - 1)
                out[(size_t)(brow0 + pr) * H + ubase + pu] = h2v;
        }
        cluster_sync_();   // publishes h1[i+1] and h2[i]; orders gs for next iter
    }
}

// ---------------------------------------------------------------
extern "C" void kernel_launch(void* const* d_in, const int* in_sizes, int n_in,
                              void* d_out, int out_size)
{
    const float* x    = (const float*)d_in[0];
    const float* h0   = (const float*)d_in[1];
    const float* c0   = (const float*)d_in[2];
    const float* Wih0 = (const float*)d_in[3];
    const float* Whh0 = (const float*)d_in[4];
    const float* bih0 = (const float*)d_in[5];
    const float* bhh0 = (const float*)d_in[6];
    const float* Wih1 = (const float*)d_in[7];
    const float* Whh1 = (const float*)d_in[8];
    const float* bih1 = (const float*)d_in[9];
    const float* bhh1 = (const float*)d_in[10];
    float* out = (float*)d_out;

    cudaFuncSetAttribute(precompute_kernel,
                         cudaFuncAttributeMaxDynamicSharedMemorySize, PRE_SMEM);
    cudaFuncSetAttribute(lstm_recurrent_kernel,
                         cudaFuncAttributeMaxDynamicSharedMemorySize, REC_SMEM);

    dim3 pgrid(T_STEPS, 4, 8);
    precompute_kernel<<<pgrid, 256, PRE_SMEM>>>(x, Wih0, bih0, bhh0);

    lstm_recurrent_kernel<<<TEAMS * 4, 384, REC_SMEM>>>(
        h0, c0, Whh0, Wih1, Whh1, bih1, bhh1, out);
}